// round 4
// baseline (speedup 1.0000x reference)
#include <cuda_runtime.h>
#include <cstdint>

#define BB   32
#define TT   336
#define NH   100
#define NM   150
#define FH   8
#define FM   16
#define HG   64
#define HL   64
#define FUT  24
#define TC   16   // timesteps per xgemm block

typedef unsigned long long u64;

// Packed fp32 ops (per-lane .rn, bitwise == scalar)
#define FMA2(d, a, b) \
    asm("fma.rn.f32x2 %0, %1, %2, %0;" : "+l"(d) : "l"(a), "l"(b))
#define ADD2(d, a) \
    asm("add.rn.f32x2 %0, %0, %1;" : "+l"(d) : "l"(a))
#define PACK2(d, v) \
    asm("mov.b64 %0, {%1, %1};" : "=l"(d) : "r"(__float_as_uint(v)))
#define UNPACK2(lo, hi, x) \
    asm("mov.b64 {%0, %1}, %2;" : "=f"(lo), "=f"(hi) : "l"(x))

#define CP_ASYNC16(smem_u32, gptr) \
    asm volatile("cp.async.cg.shared.global [%0], [%1], 16;" \
                 :: "r"(smem_u32), "l"(gptr))
#define CP_COMMIT()  asm volatile("cp.async.commit_group;")
#define CP_WAIT0()   asm volatile("cp.async.wait_group 0;")

// GNN output x: [n][t][b][hg]
__device__ float g_x[(size_t)NH * TT * BB * HG];
// Precomputed x-gates (+bias): [n][t][b][256]
__device__ float g_gates[(size_t)NH * TT * BB * 256];

// ---------------------------------------------------------------------------
// Kernel A: hetero GraphConv, one graph (b,t) per block. (unchanged)
// ---------------------------------------------------------------------------
__global__ void __launch_bounds__(256) gnn_kernel(
    const float* __restrict__ xm_all, const float* __restrict__ xh_all,
    const int* __restrict__ eh, const int* __restrict__ em,
    const float* __restrict__ Wrel_m, const float* __restrict__ brel_m,
    const float* __restrict__ Wroot_m,
    const float* __restrict__ Wrel_h, const float* __restrict__ brel_h,
    const float* __restrict__ Wroot_h,
    int Eh, int Em)
{
    __shared__ float sxh[NH * FH];
    __shared__ float sxm[NM * FM];
    __shared__ float sah[NH * FH];
    __shared__ float sam[NH * FM];
    __shared__ float swh[HG * FH];
    __shared__ float swm[HG * FM];
    __shared__ float swr[HG * FH];
    __shared__ float sb[HG];

    const int g = blockIdx.x;
    const int t = g % TT;
    const int b = g / TT;
    const int tid = threadIdx.x;

    const float* xh = xh_all + (size_t)g * NH * FH;
    const float* xm = xm_all + (size_t)g * NM * FM;

    for (int i = tid; i < NH * FH; i += 256) { sxh[i] = xh[i]; sah[i] = 0.f; }
    for (int i = tid; i < NM * FM; i += 256) sxm[i] = xm[i];
    for (int i = tid; i < NH * FM; i += 256) sam[i] = 0.f;
    for (int i = tid; i < HG * FH; i += 256) {
        swh[i] = 0.5f * Wrel_h[i];
        swr[i] = 0.5f * (Wroot_h[i] + Wroot_m[i]);
    }
    for (int i = tid; i < HG * FM; i += 256) swm[i] = 0.5f * Wrel_m[i];
    for (int i = tid; i < HG;      i += 256) sb[i]  = 0.5f * (brel_h[i] + brel_m[i]);
    __syncthreads();

    for (int e = tid; e < Eh; e += 256) {
        int s  = eh[e];
        int tg = eh[Eh + e];
        #pragma unroll
        for (int f = 0; f < FH; f++)
            atomicAdd(&sah[tg * FH + f], sxh[s * FH + f]);
    }
    for (int e = tid; e < Em; e += 256) {
        int s  = em[e];
        int tg = em[Em + e];
        #pragma unroll
        for (int f = 0; f < FM; f++)
            atomicAdd(&sam[tg * FM + f], sxm[s * FM + f]);
    }
    __syncthreads();

    for (int idx = tid; idx < NH * HG; idx += 256) {
        int n = idx / HG;
        int j = idx % HG;
        float acc = sb[j];
        #pragma unroll
        for (int k = 0; k < FH; k++)
            acc += sah[n * FH + k] * swh[j * FH + k]
                 + sxh[n * FH + k] * swr[j * FH + k];
        #pragma unroll
        for (int k = 0; k < FM; k++)
            acc += sam[n * FM + k] * swm[j * FM + k];
        float v = acc > 0.f ? acc : 0.01f * acc;
        g_x[(((size_t)n * TT + t) * BB + b) * HG + j] = v;
    }
}

// ---------------------------------------------------------------------------
// Kernel B: x-gate precompute, 2 timesteps per weight pass, 2 blocks/SM.
// ---------------------------------------------------------------------------
#define XG_SW 0                     // [k][j] stride 256 (16384 floats)
#define XG_SB 16384                 // 256
#define XG_SX (16384 + 256)         // 2 x [k][b] stride 36 (2*2304)
#define XG_FLOATS (XG_SX + 2*2304)
#define XG_BYTES  (XG_FLOATS * 4)

__global__ void __launch_bounds__(256, 2) xgemm_kernel(
    const float* __restrict__ W_ih,
    const float* __restrict__ b_ih, const float* __restrict__ b_hh)
{
    extern __shared__ float sm[];
    float* sW = sm + XG_SW;
    float* sb = sm + XG_SB;
    float* sx = sm + XG_SX;      // two buffers of 64*36

    const int n   = blockIdx.x;
    const int t0  = blockIdx.y * TC;
    const int tid = threadIdx.x;

    const float* w = W_ih + (size_t)n * 256 * 64;
    for (int i = tid; i < 16384; i += 256) {
        int j = i >> 6, k = i & 63;
        sW[k * 256 + j] = w[i];
    }
    sb[tid] = b_ih[n * 256 + tid] + b_hh[n * 256 + tid];

    const int tm = tid >> 5;          // batch group 0..7 (4 batches)
    const int tn = tid & 31;          // unit pair
    const int sb_b = tid >> 3;
    const int sb_k = (tid & 7) << 3;

    const float* xbase = g_x + ((size_t)n * TT + t0) * BB * HG;
    float* gbase = g_gates + ((size_t)n * TT + t0) * BB * 256;
    __syncthreads();

    for (int tp = 0; tp < TC / 2; tp++) {
        // stage two timesteps into sx[0], sx[1]
        #pragma unroll
        for (int tt2 = 0; tt2 < 2; tt2++) {
            const float* xt = xbase + (size_t)(2 * tp + tt2) * BB * HG;
            float* sxd = sx + tt2 * 2304;
            float4 v0 = *(const float4*)&xt[sb_b * HG + sb_k];
            float4 v1 = *(const float4*)&xt[sb_b * HG + sb_k + 4];
            sxd[(sb_k + 0) * 36 + sb_b] = v0.x;
            sxd[(sb_k + 1) * 36 + sb_b] = v0.y;
            sxd[(sb_k + 2) * 36 + sb_b] = v0.z;
            sxd[(sb_k + 3) * 36 + sb_b] = v0.w;
            sxd[(sb_k + 4) * 36 + sb_b] = v1.x;
            sxd[(sb_k + 5) * 36 + sb_b] = v1.y;
            sxd[(sb_k + 6) * 36 + sb_b] = v1.z;
            sxd[(sb_k + 7) * 36 + sb_b] = v1.w;
        }
        __syncthreads();

        u64 acc[2][4][4];   // [tt2][mi][gate]
        {
            u64 binit[4];
            #pragma unroll
            for (int gg = 0; gg < 4; gg++)
                binit[gg] = *(const u64*)&sb[gg * 64 + 2 * tn];
            #pragma unroll
            for (int tt2 = 0; tt2 < 2; tt2++)
                #pragma unroll
                for (int mi = 0; mi < 4; mi++)
                    #pragma unroll
                    for (int gg = 0; gg < 4; gg++)
                        acc[tt2][mi][gg] = binit[gg];
        }

        #pragma unroll 2
        for (int k = 0; k < 64; k++) {
            u64 wv[4];
            #pragma unroll
            for (int gg = 0; gg < 4; gg++)
                wv[gg] = *(const u64*)&sW[k * 256 + gg * 64 + 2 * tn];
            #pragma unroll
            for (int tt2 = 0; tt2 < 2; tt2++) {
                float4 xv = *(const float4*)&sx[tt2 * 2304 + k * 36 + 4 * tm];
                u64 xx[4];
                PACK2(xx[0], xv.x); PACK2(xx[1], xv.y);
                PACK2(xx[2], xv.z); PACK2(xx[3], xv.w);
                #pragma unroll
                for (int gg = 0; gg < 4; gg++)
                    #pragma unroll
                    for (int mi = 0; mi < 4; mi++)
                        FMA2(acc[tt2][mi][gg], xx[mi], wv[gg]);
            }
        }

        #pragma unroll
        for (int tt2 = 0; tt2 < 2; tt2++) {
            float* gt = gbase + (size_t)(2 * tp + tt2) * BB * 256;
            #pragma unroll
            for (int mi = 0; mi < 4; mi++)
                #pragma unroll
                for (int gg = 0; gg < 4; gg++)
                    *(u64*)&gt[(4 * tm + mi) * 256 + gg * 64 + 2 * tn] =
                        acc[tt2][mi][gg];
        }
        __syncthreads();
    }
}

// ---------------------------------------------------------------------------
// Kernel C: recurrent LSTM, k-split across warp halves.
//   warps 0-3 (kc=0): k in [0,32), acc seeded with x-gates (from SMEM, cp.async)
//   warps 4-7 (kc=1): k in [32,64), acc seeded with 0, partials -> SMEM red
//   kc=0 combines partials, applies activations, writes h (double-buffered).
// Thread within half: tm=0..3 -> batches 8tm..8tm+7, tn -> unit pair 2tn.
// ---------------------------------------------------------------------------
#define L_SW   0                        // [k][j] stride 256: 16384 floats
#define L_SH   16384                    // 2 x [k][b] stride 36: 2*2304
#define L_SG   (L_SH + 2*2304)          // 2 x 32*256 gate buffers: 2*8192
#define L_RED  (L_SG + 2*8192)          // 128 x 66: 8448
#define L_WL   (L_RED + 128*66)         // 24*64
#define L_BL   (L_WL + 24*64)
#define LS_FLOATS (L_BL + 32)
#define LS_BYTES  (LS_FLOATS * 4)

__device__ __forceinline__ float sigm(float x) {
    return 1.0f / (1.0f + __expf(-x));
}
__device__ __forceinline__ float tanh_fast(float x) {
    float xc = fminf(fmaxf(x, -15.f), 15.f);
    float e = __expf(2.0f * xc);
    return (e - 1.0f) / (e + 1.0f);
}

__global__ void __launch_bounds__(256) lstm_kernel(
    const float* __restrict__ W_hh,
    const float* __restrict__ W_lin, const float* __restrict__ b_lin,
    float* __restrict__ out)
{
    extern __shared__ float sm[];
    float* sW    = sm + L_SW;
    float* sh    = sm + L_SH;
    float* sg    = sm + L_SG;
    float* red   = sm + L_RED;
    float* sWlin = sm + L_WL;
    float* sblin = sm + L_BL;

    const int n   = blockIdx.x;
    const int tid = threadIdx.x;

    const float* whh = W_hh + (size_t)n * 256 * 64;
    for (int i = tid; i < 16384; i += 256) {
        int j = i >> 6, k = i & 63;
        sW[k * 256 + j] = whh[i];
    }
    for (int i = tid; i < FUT * HL; i += 256) sWlin[i] = W_lin[i];
    if (tid < FUT) sblin[tid] = b_lin[tid];
    for (int i = tid; i < 2304; i += 256) sh[i] = 0.f;   // h0 buffer (buf 0)

    const int kc = tid >> 7;        // 0 or 1
    const int tl = tid & 127;
    const int tm = tl >> 5;         // 0..3 -> batches 8tm..8tm+7
    const int tn = tl & 31;         // unit pair
    const int k0 = kc * 32;

    const float* gsrc = g_gates + (size_t)n * TT * BB * 256;
    const uint32_t sg_base =
        (uint32_t)__cvta_generic_to_shared(sg) + (uint32_t)tid * 128;

    // preload gates for t=0 into sg buffer 0
    {
        const float* src = gsrc + tid * 32;
        #pragma unroll
        for (int q = 0; q < 8; q++)
            CP_ASYNC16(sg_base + q * 16, src + q * 4);
        CP_COMMIT();
        CP_WAIT0();
    }

    float c[8][2];
    #pragma unroll
    for (int mi = 0; mi < 8; mi++) { c[mi][0] = 0.f; c[mi][1] = 0.f; }

    __syncthreads();

    for (int t = 0; t < TT; t++) {
        // issue gate prefetch for t+1 into the other buffer
        if (t + 1 < TT) {
            const float* src = gsrc + (size_t)(t + 1) * 8192 + tid * 32;
            uint32_t dst = sg_base + (uint32_t)(((t + 1) & 1) * 8192) * 4;
            #pragma unroll
            for (int q = 0; q < 8; q++)
                CP_ASYNC16(dst + q * 16, src + q * 4);
            CP_COMMIT();
        }

        // accumulator init
        u64 acc[8][4];
        if (kc == 0) {
            const float* sgc = sg + (t & 1) * 8192;
            #pragma unroll
            for (int mi = 0; mi < 8; mi++)
                #pragma unroll
                for (int gg = 0; gg < 4; gg++)
                    acc[mi][gg] =
                        *(const u64*)&sgc[(8 * tm + mi) * 256 + gg * 64 + 2 * tn];
        } else {
            #pragma unroll
            for (int mi = 0; mi < 8; mi++)
                #pragma unroll
                for (int gg = 0; gg < 4; gg++) acc[mi][gg] = 0ull;
        }

        // half-K GEMM
        const float* hb = sh + (t & 1) * 2304;
        #pragma unroll 2
        for (int k = 0; k < 32; k++) {
            const int kk = k0 + k;
            float4 h0 = *(const float4*)&hb[kk * 36 + 8 * tm];
            float4 h1 = *(const float4*)&hb[kk * 36 + 8 * tm + 4];
            u64 hx[8];
            PACK2(hx[0], h0.x); PACK2(hx[1], h0.y);
            PACK2(hx[2], h0.z); PACK2(hx[3], h0.w);
            PACK2(hx[4], h1.x); PACK2(hx[5], h1.y);
            PACK2(hx[6], h1.z); PACK2(hx[7], h1.w);
            #pragma unroll
            for (int gg = 0; gg < 4; gg++) {
                u64 wv = *(const u64*)&sW[kk * 256 + gg * 64 + 2 * tn];
                #pragma unroll
                for (int mi = 0; mi < 8; mi++)
                    FMA2(acc[mi][gg], hx[mi], wv);
            }
        }

        // kc=1 publishes partials
        if (kc == 1) {
            float* rd = red + tl * 66;
            #pragma unroll
            for (int mi = 0; mi < 8; mi++)
                #pragma unroll
                for (int gg = 0; gg < 4; gg++)
                    *(u64*)&rd[2 * (mi * 4 + gg)] = acc[mi][gg];
        }

        CP_WAIT0();         // gates for t+1 landed (nothing pending if t+1==TT)
        __syncthreads();    // partials + t+1 gates visible

        if (kc == 0) {
            const float* rd = red + tl * 66;
            #pragma unroll
            for (int mi = 0; mi < 8; mi++)
                #pragma unroll
                for (int gg = 0; gg < 4; gg++) {
                    u64 p = *(const u64*)&rd[2 * (mi * 4 + gg)];
                    ADD2(acc[mi][gg], p);
                }

            float* hw = sh + ((t + 1) & 1) * 2304;
            #pragma unroll
            for (int mi = 0; mi < 8; mi++) {
                float iv[2], fv[2], gv[2], ov[2];
                UNPACK2(iv[0], iv[1], acc[mi][0]);
                UNPACK2(fv[0], fv[1], acc[mi][1]);
                UNPACK2(gv[0], gv[1], acc[mi][2]);
                UNPACK2(ov[0], ov[1], acc[mi][3]);
                #pragma unroll
                for (int du = 0; du < 2; du++) {
                    float ig = sigm(iv[du]);
                    float fg = sigm(fv[du]);
                    float gg = tanh_fast(gv[du]);
                    float og = sigm(ov[du]);
                    float cc = fg * c[mi][du] + ig * gg;
                    c[mi][du] = cc;
                    hw[(2 * tn + du) * 36 + (8 * tm + mi)] = og * tanh_fast(cc);
                }
            }
        }
        __syncthreads();    // h(t+1) visible to all
    }

    // h_last is in buffer (TT & 1) == 0
    float* hl = sh;
    for (int idx = tid; idx < BB * FUT; idx += 256) {
        int b = idx / FUT;
        int f = idx % FUT;
        float acc = sblin[f];
        #pragma unroll
        for (int u = 0; u < HL; u++)
            acc += hl[u * 36 + b] * sWlin[f * HL + u];
        float v = acc > 0.f ? acc : 0.01f * acc;
        out[((size_t)b * NH + n) * FUT + f] = v;
    }
}

// ---------------------------------------------------------------------------
extern "C" void kernel_launch(void* const* d_in, const int* in_sizes, int n_in,
                              void* d_out, int out_size)
{
    const float* data_meteo = (const float*)d_in[0];
    const float* data_hydro = (const float*)d_in[1];
    const int*   eh         = (const int*)  d_in[2];
    const int*   em         = (const int*)  d_in[3];
    const float* W_rel_m    = (const float*)d_in[4];
    const float* b_rel_m    = (const float*)d_in[5];
    const float* W_root_m   = (const float*)d_in[6];
    const float* W_rel_h    = (const float*)d_in[7];
    const float* b_rel_h    = (const float*)d_in[8];
    const float* W_root_h   = (const float*)d_in[9];
    const float* W_ih       = (const float*)d_in[10];
    const float* W_hh       = (const float*)d_in[11];
    const float* b_ih       = (const float*)d_in[12];
    const float* b_hh       = (const float*)d_in[13];
    const float* W_lin      = (const float*)d_in[14];
    const float* b_lin      = (const float*)d_in[15];

    const int Eh = in_sizes[2] / 2;
    const int Em = in_sizes[3] / 2;

    gnn_kernel<<<BB * TT, 256>>>(data_meteo, data_hydro, eh, em,
                                 W_rel_m, b_rel_m, W_root_m,
                                 W_rel_h, b_rel_h, W_root_h,
                                 Eh, Em);

    cudaFuncSetAttribute(xgemm_kernel,
                         cudaFuncAttributeMaxDynamicSharedMemorySize, XG_BYTES);
    dim3 xg(NH, TT / TC);
    xgemm_kernel<<<xg, 256, XG_BYTES>>>(W_ih, b_ih, b_hh);

    cudaFuncSetAttribute(lstm_kernel,
                         cudaFuncAttributeMaxDynamicSharedMemorySize, LS_BYTES);
    lstm_kernel<<<NH, 256, LS_BYTES>>>(W_hh, W_lin, b_lin, (float*)d_out);
}